// round 8
// baseline (speedup 1.0000x reference)
#include <cuda_runtime.h>
#include <cuda_bf16.h>
#include <cstdint>
#include <cstddef>

// Problem constants
#define BB 16384
#define DD 256
#define LL 255
#define HH 8

#define NT 512       // threads per CTA (16 warps, 4M x 4N warp grid)
#define TB 128       // batch rows per CTA
#define W2_STR 68
#define W3_STR 18

// ---- smem byte offsets ----
#define A_HI_OFF 0        // 128 rows x 256 k bf16, row stride 512B, XOR swizzle (64KB)
#define A_LO_OFF 65536
#define BBUF_OFF 131072   // 2 bufs x 8KB (hi 4KB + lo 4KB)
#define STG_OFF  147456   // 128 x 68 floats (34816B)
#define W2S_OFF  182272   // 16*68*4
#define W3S_OFF  186624   // 16*18*4
#define B1S_OFF  187776   // 128*4
#define B2S_OFF  188288
#define B3S_OFF  188800   // 32*4
#define ZS_OFF   188928   // 128*17*4
#define AS_OFF   197632   // 128*17*4
#define SMEM_TOTAL 206336

// pre-split W1 tiles: 136 tiles (c,kt), each 8KB = [hi 16k x 128n swizzled 4KB][lo 4KB]
__device__ __align__(16) unsigned char g_w1t[136 * 8192];

// ============================ helpers ============================
__device__ __forceinline__ uint32_t smem_u32(const void* p) {
    uint32_t a;
    asm("{ .reg .u64 t; cvta.to.shared.u64 t, %1; cvt.u32.u64 %0, t; }" : "=r"(a) : "l"(p));
    return a;
}
__device__ __forceinline__ unsigned long long pk2(float a, float b) {
    unsigned long long r;
    asm("mov.b64 %0, {%1, %2};" : "=l"(r) : "f"(a), "f"(b));
    return r;
}
__device__ __forceinline__ void fma2(unsigned long long& d, unsigned long long a, unsigned long long b) {
    asm("fma.rn.f32x2 %0, %1, %2, %0;" : "+l"(d) : "l"(a), "l"(b));
}
__device__ __forceinline__ float2 up2(unsigned long long v) {
    float2 r;
    asm("mov.b64 {%0, %1}, %2;" : "=f"(r.x), "=f"(r.y) : "l"(v));
    return r;
}
__device__ __forceinline__ float ftanh(float v) {
    float e = __expf(2.0f * v);
    return 1.0f - __fdividef(2.0f, e + 1.0f);
}
__device__ __forceinline__ uint32_t pack_bf(float a, float b) {
    __nv_bfloat16 x = __float2bfloat16(a), y = __float2bfloat16(b);
    return (uint32_t)(*(uint16_t*)&x) | ((uint32_t)(*(uint16_t*)&y) << 16);
}
__device__ __forceinline__ void ldsm4(uint32_t* r, uint32_t a) {
    asm volatile("ldmatrix.sync.aligned.m8n8.x4.shared.b16 {%0,%1,%2,%3}, [%4];"
                 : "=r"(r[0]), "=r"(r[1]), "=r"(r[2]), "=r"(r[3]) : "r"(a));
}
__device__ __forceinline__ void ldsm4t(uint32_t* r, uint32_t a) {
    asm volatile("ldmatrix.sync.aligned.m8n8.x4.trans.shared.b16 {%0,%1,%2,%3}, [%4];"
                 : "=r"(r[0]), "=r"(r[1]), "=r"(r[2]), "=r"(r[3]) : "r"(a));
}
__device__ __forceinline__ void mma_bf16(float* d, const uint32_t* a, const uint32_t* b) {
    asm volatile("mma.sync.aligned.m16n8k16.row.col.f32.bf16.bf16.f32 "
                 "{%0,%1,%2,%3}, {%4,%5,%6,%7}, {%8,%9}, {%0,%1,%2,%3};"
                 : "+f"(d[0]), "+f"(d[1]), "+f"(d[2]), "+f"(d[3])
                 : "r"(a[0]), "r"(a[1]), "r"(a[2]), "r"(a[3]), "r"(b[0]), "r"(b[1]));
}
#define CP_ASYNC16(dst, src) \
    asm volatile("cp.async.cg.shared.global [%0], [%1], 16;" :: "r"(dst), "l"(src))
#define CP_COMMIT() asm volatile("cp.async.commit_group;" ::: "memory")
#define CP_WAIT0()  asm volatile("cp.async.wait_group 0;" ::: "memory")

// ============== prep: W1 -> split-bf16 k-major swizzled tiles ==============
__global__ void __launch_bounds__(256) prep_w1(const float* __restrict__ W1) {
    const int c = blockIdx.x, kt = blockIdx.y;
    if (kt > c) return;
    const int tix = c * (c + 1) / 2 + kt;
    unsigned char* hi = g_w1t + (size_t)tix * 8192;
    unsigned char* lo = hi + 4096;
    #pragma unroll
    for (int i = 0; i < 8; ++i) {
        int e = threadIdx.x + i * 256;            // 0..2047 = 16k x 128n
        int k = e >> 7, n = e & 127;
        int j = n >> 3, h = n & 7;
        int l = c * 16 + j, d = kt * 16 + k;
        float v = (l < LL && d <= l) ? W1[((size_t)l * DD + d) * HH + h] : 0.f;
        __nv_bfloat16 vh = __float2bfloat16(v);
        __nv_bfloat16 vl = __float2bfloat16(v - __bfloat162float(vh));
        uint32_t off = (uint32_t)k * 256 + (((uint32_t)(n >> 3) ^ (uint32_t)(k & 7)) << 4)
                     + (uint32_t)(n & 7) * 2;
        *(__nv_bfloat16*)(hi + off) = vh;
        *(__nv_bfloat16*)(lo + off) = vl;
    }
}

// ============================ main kernel ============================
extern __shared__ unsigned char smem[];

__global__ void __launch_bounds__(NT) maf_kernel(
    const float* __restrict__ x,   const float* __restrict__ ipar,
    const float* __restrict__ W1,  const float* __restrict__ b1,
    const float* __restrict__ W2,  const float* __restrict__ b2,
    const float* __restrict__ W3,  const float* __restrict__ b3,
    float* __restrict__ out, int out_size)
{
    const int tid  = threadIdx.x;
    const int warp = tid >> 5;
    const int lane = tid & 31;
    const int wm   = warp & 3;     // M-quarter: rows wm*32..+31
    const int wn   = warp >> 2;    // N-quarter: cols wn*32..+31
    const int row0 = blockIdx.x * TB;

    const uint32_t sb = smem_u32(smem);
    float* stg = (float*)(smem + STG_OFF);
    float* w2s = (float*)(smem + W2S_OFF);
    float* w3s = (float*)(smem + W3S_OFF);
    float* b1s = (float*)(smem + B1S_OFF);
    float* b2s = (float*)(smem + B2S_OFF);
    float* b3s = (float*)(smem + B3S_OFF);
    float* zs  = (float*)(smem + ZS_OFF);
    float* as_ = (float*)(smem + AS_OFF);

    // ---- fill A: x -> split bf16, XOR-swizzled, row stride 512B ----
    {
        const int r  = tid >> 2;
        const int g0 = (tid & 3) * 8;
        const float* xr = x + (size_t)(row0 + r) * DD;
        unsigned char* ah = smem + A_HI_OFF + r * 512;
        unsigned char* al = smem + A_LO_OFF + r * 512;
        #pragma unroll 4
        for (int i = 0; i < 8; ++i) {
            int g = g0 + i;
            int k0 = g * 8;
            float4 v0 = *(const float4*)(xr + k0);
            float4 v1 = *(const float4*)(xr + k0 + 4);
            float f[8] = {v0.x, v0.y, v0.z, v0.w, v1.x, v1.y, v1.z, v1.w};
            uint32_t hu[4], lu[4];
            #pragma unroll
            for (int q = 0; q < 4; ++q) {
                float a0 = f[2 * q], a1 = f[2 * q + 1];
                __nv_bfloat16 h0 = __float2bfloat16(a0), h1 = __float2bfloat16(a1);
                hu[q] = (uint32_t)(*(uint16_t*)&h0) | ((uint32_t)(*(uint16_t*)&h1) << 16);
                lu[q] = pack_bf(a0 - __bfloat162float(h0), a1 - __bfloat162float(h1));
            }
            uint32_t off = (uint32_t)((g ^ (r & 7)) << 4);
            *(uint4*)(ah + off) = make_uint4(hu[0], hu[1], hu[2], hu[3]);
            *(uint4*)(al + off) = make_uint4(lu[0], lu[1], lu[2], lu[3]);
        }
    }

    // ---- per-lane invariant addresses ----
    const int arow0 = wm * 32 + (lane & 7) + ((lane >> 3) & 1) * 8;   // mt=0 tile
    const uint32_t aBaseHi0 = sb + A_HI_OFF + (uint32_t)arow0 * 512;
    const uint32_t aBaseHi1 = aBaseHi0 + 16 * 512;
    const uint32_t aBaseLo0 = aBaseHi0 + 65536;
    const uint32_t aBaseLo1 = aBaseHi1 + 65536;
    const int aSw = (lane & 7);
    const int bk = (lane & 7) + ((lane >> 3) & 1) * 8;
    const uint32_t bRow = (uint32_t)bk * 256;

    // prefetch: one 16B op per thread covers 8KB tile
    auto prefetch = [&](int tix, int b) {
        uint32_t dst = sb + BBUF_OFF + (uint32_t)b * 8192 + (uint32_t)tid * 16;
        const unsigned char* src = g_w1t + (size_t)tix * 8192 + (size_t)tid * 16;
        CP_ASYNC16(dst, src);
    };

    prefetch(0, 0);
    CP_COMMIT();

    float alacc = 0.f;     // log_det partial for row=tid (tid<128)
    int step = 0;

    for (int c = 0; c < 16; ++c) {
        const int l0 = c * 16;

        // ---- small per-layer weights ----
        if (tid < 256) {
            int jj = tid >> 4, q = tid & 15;
            float4 v4 = make_float4(0.f, 0.f, 0.f, 0.f);
            if (l0 + jj < LL) v4 = ((const float4*)W2)[(l0 + jj) * 16 + q];
            *(float4*)(w2s + jj * W2_STR + q * 4) = v4;
            w3s[jj * W3_STR + q] = (l0 + jj < LL) ? W3[(l0 + jj) * 16 + q] : 0.f;
            if (tid < 128) {
                int jb = tid >> 3, h = tid & 7;
                b1s[tid] = (l0 + jb < LL) ? b1[(l0 + jb) * 8 + h] : 0.f;
                b2s[tid] = (l0 + jb < LL) ? b2[(l0 + jb) * 8 + h] : 0.f;
            }
            if (tid < 32) {
                int j3 = tid >> 1, k3 = tid & 1;
                b3s[tid] = (l0 + j3 < LL) ? b3[(l0 + j3) * 2 + k3] : 0.f;
            }
        }

        float acc[2][4][4];
        #pragma unroll
        for (int mt = 0; mt < 2; ++mt)
            #pragma unroll
            for (int t = 0; t < 4; ++t)
                #pragma unroll
                for (int q = 0; q < 4; ++q) acc[mt][t][q] = 0.f;

        // ---- k loop: one 16-wide step per tile ----
        for (int kt = 0; kt <= c; ++kt) {
            CP_WAIT0();
            __syncthreads();
            {
                int ntix = (kt < c) ? (c * (c + 1) / 2 + kt + 1)
                         : ((c < 15) ? (c + 1) * (c + 2) / 2 : -1);
                if (ntix >= 0) prefetch(ntix, (step + 1) & 1);
                CP_COMMIT();
            }
            const uint32_t bufHi = sb + BBUF_OFF + (uint32_t)(step & 1) * 8192;
            const uint32_t bufLo = bufHi + 4096;

            // A fragments (2 m-tiles x hi/lo)
            uint32_t ah[2][4], alo[2][4];
            {
                uint32_t offk = (uint32_t)(((2 * kt + (lane >> 4)) ^ aSw) << 4);
                ldsm4(ah[0],  aBaseHi0 + offk);
                ldsm4(ah[1],  aBaseHi1 + offk);
                ldsm4(alo[0], aBaseLo0 + offk);
                ldsm4(alo[1], aBaseLo1 + offk);
            }
            // B fragments: 2 pair-tiles x hi/lo (cols wn*32..+31)
            uint32_t bh[2][4], bl[2][4];
            #pragma unroll
            for (int p = 0; p < 2; ++p) {
                uint32_t cidx = (uint32_t)(wn * 4 + 2 * p + (lane >> 4));
                uint32_t off  = bRow + (((cidx ^ (uint32_t)(lane & 7))) << 4);
                ldsm4t(bh[p], bufHi + off);
                ldsm4t(bl[p], bufLo + off);
            }
            // MMAs: hh + hl + lh
            #pragma unroll
            for (int mt = 0; mt < 2; ++mt) {
                #pragma unroll
                for (int p = 0; p < 2; ++p) {
                    mma_bf16(acc[mt][2 * p],     ah[mt],  &bh[p][0]);
                    mma_bf16(acc[mt][2 * p + 1], ah[mt],  &bh[p][2]);
                    mma_bf16(acc[mt][2 * p],     ah[mt],  &bl[p][0]);
                    mma_bf16(acc[mt][2 * p + 1], ah[mt],  &bl[p][2]);
                    mma_bf16(acc[mt][2 * p],     alo[mt], &bh[p][0]);
                    mma_bf16(acc[mt][2 * p + 1], alo[mt], &bh[p][2]);
                }
            }
            step++;
        }

        // ---- epilogue: two 64-col passes (wn pairs {0,1} then {2,3}) ----
        #pragma unroll
        for (int p = 0; p < 2; ++p) {
            __syncthreads();
            if ((wn >> 1) == p) {
                const int cbase = (wn & 1) * 32;
                #pragma unroll
                for (int mt = 0; mt < 2; ++mt) {
                    int r = wm * 32 + mt * 16 + (lane >> 2);
                    int cc = (lane & 3) * 2;
                    #pragma unroll
                    for (int t = 0; t < 4; ++t) {
                        *(float2*)(stg + r * 68 + cbase + t * 8 + cc) =
                            make_float2(acc[mt][t][0], acc[mt][t][1]);
                        *(float2*)(stg + (r + 8) * 68 + cbase + t * 8 + cc) =
                            make_float2(acc[mt][t][2], acc[mt][t][3]);
                    }
                }
            }
            __syncthreads();
            // jobs: 1024 = 128 rows x 8 local layers, 512 threads -> 2 iters
            #pragma unroll
            for (int it = 0; it < 2; ++it) {
                int job = it * 512 + tid;
                int j   = job & 7;
                int row = job >> 3;
                int jloc = p * 8 + j;
                int l = l0 + jloc;
                float4 q0 = *(const float4*)(stg + row * 68 + j * 8);
                float4 q1 = *(const float4*)(stg + row * 68 + j * 8 + 4);
                if (l < LL) {
                    float pre[8] = {q0.x, q0.y, q0.z, q0.w, q1.x, q1.y, q1.z, q1.w};
                    float h1v[8];
                    #pragma unroll
                    for (int h = 0; h < 8; ++h)
                        h1v[h] = ftanh(pre[h] + b1s[jloc * 8 + h]);
                    unsigned long long a2[4];
                    a2[0] = pk2(b2s[jloc * 8 + 0], b2s[jloc * 8 + 1]);
                    a2[1] = pk2(b2s[jloc * 8 + 2], b2s[jloc * 8 + 3]);
                    a2[2] = pk2(b2s[jloc * 8 + 4], b2s[jloc * 8 + 5]);
                    a2[3] = pk2(b2s[jloc * 8 + 6], b2s[jloc * 8 + 7]);
                    #pragma unroll
                    for (int h = 0; h < 8; ++h) {
                        ulonglong2 rA = *(const ulonglong2*)(w2s + jloc * W2_STR + h * 8);
                        ulonglong2 rB = *(const ulonglong2*)(w2s + jloc * W2_STR + h * 8 + 4);
                        unsigned long long hp = pk2(h1v[h], h1v[h]);
                        fma2(a2[0], hp, rA.x); fma2(a2[1], hp, rA.y);
                        fma2(a2[2], hp, rB.x); fma2(a2[3], hp, rB.y);
                    }
                    float mu = b3s[jloc * 2 + 0], al = b3s[jloc * 2 + 1];
                    #pragma unroll
                    for (int hp4 = 0; hp4 < 4; ++hp4) {
                        float2 pr = up2(a2[hp4]);
                        float h2a = ftanh(pr.x), h2b = ftanh(pr.y);
                        mu += h2a * w3s[jloc * W3_STR + (2 * hp4) * 2]
                            + h2b * w3s[jloc * W3_STR + (2 * hp4 + 1) * 2];
                        al += h2a * w3s[jloc * W3_STR + (2 * hp4) * 2 + 1]
                            + h2b * w3s[jloc * W3_STR + (2 * hp4 + 1) * 2 + 1];
                    }
                    // xn = x[row][l+1] from split-bf16 A
                    int k = l + 1;
                    uint32_t xo = (uint32_t)row * 512
                                + (uint32_t)((((k >> 3) ^ (row & 7))) << 4)
                                + (uint32_t)(k & 7) * 2;
                    float xn = __bfloat162float(*(const __nv_bfloat16*)(smem + A_HI_OFF + xo))
                             + __bfloat162float(*(const __nv_bfloat16*)(smem + A_LO_OFF + xo));
                    float zv = (xn - mu) * __expf(-al);
                    zs[row * 17 + (15 - jloc)] = zv;
                    as_[row * 17 + jloc] = al;
                } else {
                    as_[row * 17 + jloc] = 0.f;
                }
            }
        }
        __syncthreads();
        // ---- flush z (coalesced 16-col groups) + alpha accumulation ----
        {
            const int cb = 239 - l0;
            #pragma unroll
            for (int i = 0; i < 4; ++i) {
                int v = tid + i * 512;     // 2048
                int r = v >> 4, cc = v & 15;
                int col = cb + cc;
                if (col >= 0)
                    out[(size_t)(row0 + r) * DD + col] = zs[r * 17 + cc];
            }
            if (tid < 128) {
                float s = 0.f;
                #pragma unroll
                for (int jj = 0; jj < 16; ++jj) s += as_[tid * 17 + jj];
                alacc += s;
            }
        }
    }

    // ---- finals: col 255 + log_det ----
    if (tid < 128) {
        int r = tid;
        float ip0 = ipar[0], ip1 = ipar[1];
        uint32_t xo = (uint32_t)r * 512 + (uint32_t)(((0 ^ (r & 7))) << 4);
        float x0 = __bfloat162float(*(const __nv_bfloat16*)(smem + A_HI_OFF + xo))
                 + __bfloat162float(*(const __nv_bfloat16*)(smem + A_LO_OFF + xo));
        out[(size_t)(row0 + r) * DD + 255] = (x0 - ip0) * __expf(-ip1);
        if (out_size > BB * DD)
            out[(size_t)BB * DD + row0 + r] = -(ip1 + alacc);
    }
}

extern "C" void kernel_launch(void* const* d_in, const int* in_sizes, int n_in,
                              void* d_out, int out_size)
{
    const float* x    = (const float*)d_in[0];
    const float* ipar = (const float*)d_in[1];
    const float* W1   = (const float*)d_in[2];
    const float* b1   = (const float*)d_in[3];
    const float* W2   = (const float*)d_in[4];
    const float* b2   = (const float*)d_in[5];
    const float* W3   = (const float*)d_in[6];
    const float* b3   = (const float*)d_in[7];
    float* out = (float*)d_out;

    prep_w1<<<dim3(16, 16), 256>>>(W1);
    cudaFuncSetAttribute(maf_kernel, cudaFuncAttributeMaxDynamicSharedMemorySize, SMEM_TOTAL);
    maf_kernel<<<BB / TB, NT, SMEM_TOTAL>>>(x, ipar, W1, b1, W2, b2, W3, b3, out, out_size);
}

// round 9
// speedup vs baseline: 1.0656x; 1.0656x over previous
#include <cuda_runtime.h>
#include <cuda_bf16.h>
#include <cstdint>
#include <cstddef>

// Problem constants
#define BB 16384
#define DD 256
#define LL 255
#define HH 8

#define NT 256       // threads per CTA (8 warps, 2M x 4N warp grid)
#define TB 64        // batch rows per CTA
#define W2_STR 68
#define W3_STR 18

// ---- smem byte offsets (total 112KB -> 2 CTAs/SM) ----
#define A_HI_OFF 0        // 64 rows x 256 k bf16, row stride 512B, XOR swizzle (32KB)
#define A_LO_OFF 32768
#define BBUF_OFF 65536    // 2 bufs x 8KB (hi 4KB + lo 4KB)
#define STG_OFF  81920    // 64 x 68 floats (17408B)
#define W2S_OFF  99328    // 16*68*4
#define W3S_OFF  103680   // 16*18*4
#define B1S_OFF  104832   // 128*4
#define B2S_OFF  105344
#define B3S_OFF  105856   // 32*4
#define ZS_OFF   105984   // 64*17*4
#define AS_OFF   110336   // 64*17*4
#define SMEM_TOTAL 114688

// pre-split W1 tiles: 136 tiles (c,kt), each 8KB = [hi 16k x 128n swizzled 4KB][lo 4KB]
__device__ __align__(16) unsigned char g_w1t[136 * 8192];

// ============================ helpers ============================
__device__ __forceinline__ uint32_t smem_u32(const void* p) {
    uint32_t a;
    asm("{ .reg .u64 t; cvta.to.shared.u64 t, %1; cvt.u32.u64 %0, t; }" : "=r"(a) : "l"(p));
    return a;
}
__device__ __forceinline__ unsigned long long pk2(float a, float b) {
    unsigned long long r;
    asm("mov.b64 %0, {%1, %2};" : "=l"(r) : "f"(a), "f"(b));
    return r;
}
__device__ __forceinline__ void fma2(unsigned long long& d, unsigned long long a, unsigned long long b) {
    asm("fma.rn.f32x2 %0, %1, %2, %0;" : "+l"(d) : "l"(a), "l"(b));
}
__device__ __forceinline__ float2 up2(unsigned long long v) {
    float2 r;
    asm("mov.b64 {%0, %1}, %2;" : "=f"(r.x), "=f"(r.y) : "l"(v));
    return r;
}
__device__ __forceinline__ float ftanh(float v) {
    float e = __expf(2.0f * v);
    return 1.0f - __fdividef(2.0f, e + 1.0f);
}
__device__ __forceinline__ uint32_t pack_bf(float a, float b) {
    __nv_bfloat16 x = __float2bfloat16(a), y = __float2bfloat16(b);
    return (uint32_t)(*(uint16_t*)&x) | ((uint32_t)(*(uint16_t*)&y) << 16);
}
__device__ __forceinline__ void ldsm4(uint32_t* r, uint32_t a) {
    asm volatile("ldmatrix.sync.aligned.m8n8.x4.shared.b16 {%0,%1,%2,%3}, [%4];"
                 : "=r"(r[0]), "=r"(r[1]), "=r"(r[2]), "=r"(r[3]) : "r"(a));
}
__device__ __forceinline__ void ldsm4t(uint32_t* r, uint32_t a) {
    asm volatile("ldmatrix.sync.aligned.m8n8.x4.trans.shared.b16 {%0,%1,%2,%3}, [%4];"
                 : "=r"(r[0]), "=r"(r[1]), "=r"(r[2]), "=r"(r[3]) : "r"(a));
}
__device__ __forceinline__ void mma_bf16(float* d, const uint32_t* a, const uint32_t* b) {
    asm volatile("mma.sync.aligned.m16n8k16.row.col.f32.bf16.bf16.f32 "
                 "{%0,%1,%2,%3}, {%4,%5,%6,%7}, {%8,%9}, {%0,%1,%2,%3};"
                 : "+f"(d[0]), "+f"(d[1]), "+f"(d[2]), "+f"(d[3])
                 : "r"(a[0]), "r"(a[1]), "r"(a[2]), "r"(a[3]), "r"(b[0]), "r"(b[1]));
}
#define CP_ASYNC16(dst, src) \
    asm volatile("cp.async.cg.shared.global [%0], [%1], 16;" :: "r"(dst), "l"(src))
#define CP_COMMIT() asm volatile("cp.async.commit_group;" ::: "memory")
#define CP_WAIT0()  asm volatile("cp.async.wait_group 0;" ::: "memory")

// ============== prep: W1 -> split-bf16 k-major swizzled tiles ==============
__global__ void __launch_bounds__(256) prep_w1(const float* __restrict__ W1) {
    const int c = blockIdx.x, kt = blockIdx.y;
    if (kt > c) return;
    const int tix = c * (c + 1) / 2 + kt;
    unsigned char* hi = g_w1t + (size_t)tix * 8192;
    unsigned char* lo = hi + 4096;
    #pragma unroll
    for (int i = 0; i < 8; ++i) {
        int e = threadIdx.x + i * 256;            // 0..2047 = 16k x 128n
        int k = e >> 7, n = e & 127;
        int j = n >> 3, h = n & 7;
        int l = c * 16 + j, d = kt * 16 + k;
        float v = (l < LL && d <= l) ? W1[((size_t)l * DD + d) * HH + h] : 0.f;
        __nv_bfloat16 vh = __float2bfloat16(v);
        __nv_bfloat16 vl = __float2bfloat16(v - __bfloat162float(vh));
        uint32_t off = (uint32_t)k * 256 + (((uint32_t)(n >> 3) ^ (uint32_t)(k & 7)) << 4)
                     + (uint32_t)(n & 7) * 2;
        *(__nv_bfloat16*)(hi + off) = vh;
        *(__nv_bfloat16*)(lo + off) = vl;
    }
}

// ============================ main kernel ============================
extern __shared__ unsigned char smem[];

__global__ void __launch_bounds__(NT, 2) maf_kernel(
    const float* __restrict__ x,   const float* __restrict__ ipar,
    const float* __restrict__ W1,  const float* __restrict__ b1,
    const float* __restrict__ W2,  const float* __restrict__ b2,
    const float* __restrict__ W3,  const float* __restrict__ b3,
    float* __restrict__ out, int out_size)
{
    const int tid  = threadIdx.x;
    const int warp = tid >> 5;
    const int lane = tid & 31;
    const int wm   = warp >> 2;    // M-half: rows wm*32..+31
    const int wn   = warp & 3;     // N-quarter: cols wn*32..+31
    const int row0 = blockIdx.x * TB;

    const uint32_t sb = smem_u32(smem);
    float* stg = (float*)(smem + STG_OFF);
    float* w2s = (float*)(smem + W2S_OFF);
    float* w3s = (float*)(smem + W3S_OFF);
    float* b1s = (float*)(smem + B1S_OFF);
    float* b2s = (float*)(smem + B2S_OFF);
    float* b3s = (float*)(smem + B3S_OFF);
    float* zs  = (float*)(smem + ZS_OFF);
    float* as_ = (float*)(smem + AS_OFF);

    // ---- fill A: x -> split bf16, XOR-swizzled, row stride 512B ----
    {
        const int r  = tid >> 2;              // 0..63
        const int g0 = (tid & 3) * 8;
        const float* xr = x + (size_t)(row0 + r) * DD;
        unsigned char* ah = smem + A_HI_OFF + r * 512;
        unsigned char* al = smem + A_LO_OFF + r * 512;
        #pragma unroll 4
        for (int i = 0; i < 8; ++i) {
            int g = g0 + i;
            int k0 = g * 8;
            float4 v0 = *(const float4*)(xr + k0);
            float4 v1 = *(const float4*)(xr + k0 + 4);
            float f[8] = {v0.x, v0.y, v0.z, v0.w, v1.x, v1.y, v1.z, v1.w};
            uint32_t hu[4], lu[4];
            #pragma unroll
            for (int q = 0; q < 4; ++q) {
                float a0 = f[2 * q], a1 = f[2 * q + 1];
                __nv_bfloat16 h0 = __float2bfloat16(a0), h1 = __float2bfloat16(a1);
                hu[q] = (uint32_t)(*(uint16_t*)&h0) | ((uint32_t)(*(uint16_t*)&h1) << 16);
                lu[q] = pack_bf(a0 - __bfloat162float(h0), a1 - __bfloat162float(h1));
            }
            uint32_t off = (uint32_t)((g ^ (r & 7)) << 4);
            *(uint4*)(ah + off) = make_uint4(hu[0], hu[1], hu[2], hu[3]);
            *(uint4*)(al + off) = make_uint4(lu[0], lu[1], lu[2], lu[3]);
        }
    }

    // ---- per-lane invariant addresses ----
    const int arow0 = wm * 32 + (lane & 7) + ((lane >> 3) & 1) * 8;   // mt=0 tile
    const uint32_t aBaseHi0 = sb + A_HI_OFF + (uint32_t)arow0 * 512;
    const uint32_t aBaseHi1 = aBaseHi0 + 16 * 512;
    const uint32_t aBaseLo0 = aBaseHi0 + 32768;
    const uint32_t aBaseLo1 = aBaseHi1 + 32768;
    const int aSw = (lane & 7);
    const int bk = (lane & 7) + ((lane >> 3) & 1) * 8;
    const uint32_t bRow = (uint32_t)bk * 256;

    // prefetch: 32B per thread covers 8KB tile
    auto prefetch = [&](int tix, int b) {
        uint32_t dst = sb + BBUF_OFF + (uint32_t)b * 8192 + (uint32_t)tid * 32;
        const unsigned char* src = g_w1t + (size_t)tix * 8192 + (size_t)tid * 32;
        CP_ASYNC16(dst, src);
        CP_ASYNC16(dst + 16, src + 16);
    };

    prefetch(0, 0);
    CP_COMMIT();

    float alacc = 0.f;     // log_det partial for row=tid (tid<64)
    int step = 0;

    for (int c = 0; c < 16; ++c) {
        const int l0 = c * 16;

        // ---- small per-layer weights ----
        {
            int jj = tid >> 4, q = tid & 15;
            float4 v4 = make_float4(0.f, 0.f, 0.f, 0.f);
            if (l0 + jj < LL) v4 = ((const float4*)W2)[(l0 + jj) * 16 + q];
            *(float4*)(w2s + jj * W2_STR + q * 4) = v4;
            w3s[jj * W3_STR + q] = (l0 + jj < LL) ? W3[(l0 + jj) * 16 + q] : 0.f;
            if (tid < 128) {
                int jb = tid >> 3, h = tid & 7;
                b1s[tid] = (l0 + jb < LL) ? b1[(l0 + jb) * 8 + h] : 0.f;
                b2s[tid] = (l0 + jb < LL) ? b2[(l0 + jb) * 8 + h] : 0.f;
            }
            if (tid < 32) {
                int j3 = tid >> 1, k3 = tid & 1;
                b3s[tid] = (l0 + j3 < LL) ? b3[(l0 + j3) * 2 + k3] : 0.f;
            }
        }

        float acc[2][4][4];
        #pragma unroll
        for (int mt = 0; mt < 2; ++mt)
            #pragma unroll
            for (int t = 0; t < 4; ++t)
                #pragma unroll
                for (int q = 0; q < 4; ++q) acc[mt][t][q] = 0.f;

        // ---- k loop: one 16-wide step per tile ----
        for (int kt = 0; kt <= c; ++kt) {
            CP_WAIT0();
            __syncthreads();
            {
                int ntix = (kt < c) ? (c * (c + 1) / 2 + kt + 1)
                         : ((c < 15) ? (c + 1) * (c + 2) / 2 : -1);
                if (ntix >= 0) prefetch(ntix, (step + 1) & 1);
                CP_COMMIT();
            }
            const uint32_t bufHi = sb + BBUF_OFF + (uint32_t)(step & 1) * 8192;
            const uint32_t bufLo = bufHi + 4096;

            // A fragments (2 m-tiles x hi/lo)
            uint32_t ah[2][4], alo[2][4];
            {
                uint32_t offk = (uint32_t)(((2 * kt + (lane >> 4)) ^ aSw) << 4);
                ldsm4(ah[0],  aBaseHi0 + offk);
                ldsm4(ah[1],  aBaseHi1 + offk);
                ldsm4(alo[0], aBaseLo0 + offk);
                ldsm4(alo[1], aBaseLo1 + offk);
            }
            // B fragments: 2 pair-tiles x hi/lo (cols wn*32..+31)
            uint32_t bh[2][4], bl[2][4];
            #pragma unroll
            for (int p = 0; p < 2; ++p) {
                uint32_t cidx = (uint32_t)(wn * 4 + 2 * p + (lane >> 4));
                uint32_t off  = bRow + (((cidx ^ (uint32_t)(lane & 7))) << 4);
                ldsm4t(bh[p], bufHi + off);
                ldsm4t(bl[p], bufLo + off);
            }
            // MMAs: hh + hl + lh
            #pragma unroll
            for (int mt = 0; mt < 2; ++mt) {
                #pragma unroll
                for (int p = 0; p < 2; ++p) {
                    mma_bf16(acc[mt][2 * p],     ah[mt],  &bh[p][0]);
                    mma_bf16(acc[mt][2 * p + 1], ah[mt],  &bh[p][2]);
                    mma_bf16(acc[mt][2 * p],     ah[mt],  &bl[p][0]);
                    mma_bf16(acc[mt][2 * p + 1], ah[mt],  &bl[p][2]);
                    mma_bf16(acc[mt][2 * p],     alo[mt], &bh[p][0]);
                    mma_bf16(acc[mt][2 * p + 1], alo[mt], &bh[p][2]);
                }
            }
            step++;
        }

        // ---- epilogue: two 64-col passes (wn pairs {0,1} then {2,3}) ----
        #pragma unroll
        for (int p = 0; p < 2; ++p) {
            __syncthreads();
            if ((wn >> 1) == p) {
                const int cbase = (wn & 1) * 32;
                #pragma unroll
                for (int mt = 0; mt < 2; ++mt) {
                    int r = wm * 32 + mt * 16 + (lane >> 2);
                    int cc = (lane & 3) * 2;
                    #pragma unroll
                    for (int t = 0; t < 4; ++t) {
                        *(float2*)(stg + r * 68 + cbase + t * 8 + cc) =
                            make_float2(acc[mt][t][0], acc[mt][t][1]);
                        *(float2*)(stg + (r + 8) * 68 + cbase + t * 8 + cc) =
                            make_float2(acc[mt][t][2], acc[mt][t][3]);
                    }
                }
            }
            __syncthreads();
            // jobs: 512 = 64 rows x 8 local layers, 256 threads -> 2 iters
            #pragma unroll
            for (int it = 0; it < 2; ++it) {
                int job = it * 256 + tid;
                int j   = job & 7;
                int row = job >> 3;
                int jloc = p * 8 + j;
                int l = l0 + jloc;
                float4 q0 = *(const float4*)(stg + row * 68 + j * 8);
                float4 q1 = *(const float4*)(stg + row * 68 + j * 8 + 4);
                if (l < LL) {
                    float pre[8] = {q0.x, q0.y, q0.z, q0.w, q1.x, q1.y, q1.z, q1.w};
                    float h1v[8];
                    #pragma unroll
                    for (int h = 0; h < 8; ++h)
                        h1v[h] = ftanh(pre[h] + b1s[jloc * 8 + h]);
                    unsigned long long a2[4];
                    a2[0] = pk2(b2s[jloc * 8 + 0], b2s[jloc * 8 + 1]);
                    a2[1] = pk2(b2s[jloc * 8 + 2], b2s[jloc * 8 + 3]);
                    a2[2] = pk2(b2s[jloc * 8 + 4], b2s[jloc * 8 + 5]);
                    a2[3] = pk2(b2s[jloc * 8 + 6], b2s[jloc * 8 + 7]);
                    #pragma unroll
                    for (int h = 0; h < 8; ++h) {
                        ulonglong2 rA = *(const ulonglong2*)(w2s + jloc * W2_STR + h * 8);
                        ulonglong2 rB = *(const ulonglong2*)(w2s + jloc * W2_STR + h * 8 + 4);
                        unsigned long long hp = pk2(h1v[h], h1v[h]);
                        fma2(a2[0], hp, rA.x); fma2(a2[1], hp, rA.y);
                        fma2(a2[2], hp, rB.x); fma2(a2[3], hp, rB.y);
                    }
                    float mu = b3s[jloc * 2 + 0], al = b3s[jloc * 2 + 1];
                    #pragma unroll
                    for (int hp4 = 0; hp4 < 4; ++hp4) {
                        float2 pr = up2(a2[hp4]);
                        float h2a = ftanh(pr.x), h2b = ftanh(pr.y);
                        mu += h2a * w3s[jloc * W3_STR + (2 * hp4) * 2]
                            + h2b * w3s[jloc * W3_STR + (2 * hp4 + 1) * 2];
                        al += h2a * w3s[jloc * W3_STR + (2 * hp4) * 2 + 1]
                            + h2b * w3s[jloc * W3_STR + (2 * hp4 + 1) * 2 + 1];
                    }
                    // xn = x[row][l+1] from split-bf16 A
                    int k = l + 1;
                    uint32_t xo = (uint32_t)row * 512
                                + (uint32_t)((((k >> 3) ^ (row & 7))) << 4)
                                + (uint32_t)(k & 7) * 2;
                    float xn = __bfloat162float(*(const __nv_bfloat16*)(smem + A_HI_OFF + xo))
                             + __bfloat162float(*(const __nv_bfloat16*)(smem + A_LO_OFF + xo));
                    float zv = (xn - mu) * __expf(-al);
                    zs[row * 17 + (15 - jloc)] = zv;
                    as_[row * 17 + jloc] = al;
                } else {
                    as_[row * 17 + jloc] = 0.f;
                }
            }
        }
        __syncthreads();
        // ---- flush z (coalesced 16-col groups) + alpha accumulation ----
        {
            const int cb = 239 - l0;
            #pragma unroll
            for (int i = 0; i < 4; ++i) {
                int v = tid + i * 256;     // 1024
                int r = v >> 4, cc = v & 15;
                int col = cb + cc;
                if (col >= 0)
                    out[(size_t)(row0 + r) * DD + col] = zs[r * 17 + cc];
            }
            if (tid < 64) {
                float s = 0.f;
                #pragma unroll
                for (int jj = 0; jj < 16; ++jj) s += as_[tid * 17 + jj];
                alacc += s;
            }
        }
    }

    // ---- finals: col 255 + log_det ----
    if (tid < 64) {
        int r = tid;
        float ip0 = ipar[0], ip1 = ipar[1];
        uint32_t xo = (uint32_t)r * 512 + (uint32_t)(((0 ^ (r & 7))) << 4);
        float x0 = __bfloat162float(*(const __nv_bfloat16*)(smem + A_HI_OFF + xo))
                 + __bfloat162float(*(const __nv_bfloat16*)(smem + A_LO_OFF + xo));
        out[(size_t)(row0 + r) * DD + 255] = (x0 - ip0) * __expf(-ip1);
        if (out_size > BB * DD)
            out[(size_t)BB * DD + row0 + r] = -(ip1 + alacc);
    }
}

extern "C" void kernel_launch(void* const* d_in, const int* in_sizes, int n_in,
                              void* d_out, int out_size)
{
    const float* x    = (const float*)d_in[0];
    const float* ipar = (const float*)d_in[1];
    const float* W1   = (const float*)d_in[2];
    const float* b1   = (const float*)d_in[3];
    const float* W2   = (const float*)d_in[4];
    const float* b2   = (const float*)d_in[5];
    const float* W3   = (const float*)d_in[6];
    const float* b3   = (const float*)d_in[7];
    float* out = (float*)d_out;

    prep_w1<<<dim3(16, 16), 256>>>(W1);
    cudaFuncSetAttribute(maf_kernel, cudaFuncAttributeMaxDynamicSharedMemorySize, SMEM_TOTAL);
    maf_kernel<<<BB / TB, NT, SMEM_TOTAL>>>(x, ipar, W1, b1, W2, b2, W3, b3, out, out_size);
}

// round 10
// speedup vs baseline: 1.3227x; 1.2413x over previous
#include <cuda_runtime.h>
#include <cuda_fp16.h>
#include <cstdint>
#include <cstddef>

// Problem constants
#define BB 16384
#define DD 256
#define LL 255
#define HH 8

#define NT 256       // threads per CTA (8 warps, 2M x 4N warp grid)
#define TB 64        // batch rows per CTA
#define W2_STR 68
#define W3_STR 18

// ---- smem byte offsets (total ~76KB -> 2 CTAs/SM) ----
#define A_OFF    0        // 64 rows x 256 k fp16, row stride 512B, XOR swizzle (32KB)
#define BBUF_OFF 32768    // 2 bufs x 4KB
#define XC_OFF   40960    // 64 x 17 fp32 x-columns for epilogue (4352B)
#define STG_OFF  45312    // 64 x 68 floats (17408B)
#define W2S_OFF  62720    // 16*68*4
#define W3S_OFF  67072    // 16*18*4
#define B1S_OFF  68224    // 128*4
#define B2S_OFF  68736
#define B3S_OFF  69248    // 32*4
#define ZS_OFF   69376    // 64*17*4
#define AS_OFF   73728    // 64*17*4
#define SMEM_TOTAL 78080

// pre-converted W1 tiles: 136 tiles (c,kt), each 4KB fp16 16k x 128n swizzled
__device__ __align__(16) unsigned char g_w1t[136 * 4096];

// ============================ helpers ============================
__device__ __forceinline__ uint32_t smem_u32(const void* p) {
    uint32_t a;
    asm("{ .reg .u64 t; cvta.to.shared.u64 t, %1; cvt.u32.u64 %0, t; }" : "=r"(a) : "l"(p));
    return a;
}
__device__ __forceinline__ unsigned long long pk2(float a, float b) {
    unsigned long long r;
    asm("mov.b64 %0, {%1, %2};" : "=l"(r) : "f"(a), "f"(b));
    return r;
}
__device__ __forceinline__ void fma2(unsigned long long& d, unsigned long long a, unsigned long long b) {
    asm("fma.rn.f32x2 %0, %1, %2, %0;" : "+l"(d) : "l"(a), "l"(b));
}
__device__ __forceinline__ float2 up2(unsigned long long v) {
    float2 r;
    asm("mov.b64 {%0, %1}, %2;" : "=f"(r.x), "=f"(r.y) : "l"(v));
    return r;
}
// hardware tanh approximation (sm_75+), rel err ~2^-11
__device__ __forceinline__ float ftanha(float v) {
    float r;
    asm("tanh.approx.f32 %0, %1;" : "=f"(r) : "f"(v));
    return r;
}
__device__ __forceinline__ uint32_t pack_h2(float a, float b) {
    __half2 h = __floats2half2_rn(a, b);
    return *(uint32_t*)&h;
}
__device__ __forceinline__ void ldsm4(uint32_t* r, uint32_t a) {
    asm volatile("ldmatrix.sync.aligned.m8n8.x4.shared.b16 {%0,%1,%2,%3}, [%4];"
                 : "=r"(r[0]), "=r"(r[1]), "=r"(r[2]), "=r"(r[3]) : "r"(a));
}
__device__ __forceinline__ void ldsm4t(uint32_t* r, uint32_t a) {
    asm volatile("ldmatrix.sync.aligned.m8n8.x4.trans.shared.b16 {%0,%1,%2,%3}, [%4];"
                 : "=r"(r[0]), "=r"(r[1]), "=r"(r[2]), "=r"(r[3]) : "r"(a));
}
__device__ __forceinline__ void mma_f16(float* d, const uint32_t* a, const uint32_t* b) {
    asm volatile("mma.sync.aligned.m16n8k16.row.col.f32.f16.f16.f32 "
                 "{%0,%1,%2,%3}, {%4,%5,%6,%7}, {%8,%9}, {%0,%1,%2,%3};"
                 : "+f"(d[0]), "+f"(d[1]), "+f"(d[2]), "+f"(d[3])
                 : "r"(a[0]), "r"(a[1]), "r"(a[2]), "r"(a[3]), "r"(b[0]), "r"(b[1]));
}
#define CP_ASYNC16(dst, src) \
    asm volatile("cp.async.cg.shared.global [%0], [%1], 16;" :: "r"(dst), "l"(src))
#define CP_COMMIT() asm volatile("cp.async.commit_group;" ::: "memory")
#define CP_WAIT0()  asm volatile("cp.async.wait_group 0;" ::: "memory")

// ============== prep: W1 -> fp16 k-major swizzled tiles ==============
__global__ void __launch_bounds__(256) prep_w1(const float* __restrict__ W1) {
    const int c = blockIdx.x, kt = blockIdx.y;
    if (kt > c) return;
    const int tix = c * (c + 1) / 2 + kt;
    unsigned char* dst = g_w1t + (size_t)tix * 4096;
    #pragma unroll
    for (int i = 0; i < 8; ++i) {
        int e = threadIdx.x + i * 256;            // 0..2047 = 16k x 128n
        int k = e >> 7, n = e & 127;
        int j = n >> 3, h = n & 7;
        int l = c * 16 + j, d = kt * 16 + k;
        float v = (l < LL && d <= l) ? W1[((size_t)l * DD + d) * HH + h] : 0.f;
        uint32_t off = (uint32_t)k * 256 + (((uint32_t)(n >> 3) ^ (uint32_t)(k & 7)) << 4)
                     + (uint32_t)(n & 7) * 2;
        *(__half*)(dst + off) = __float2half(v);
    }
}

// ============================ main kernel ============================
extern __shared__ unsigned char smem[];

__global__ void __launch_bounds__(NT, 2) maf_kernel(
    const float* __restrict__ x,   const float* __restrict__ ipar,
    const float* __restrict__ W1,  const float* __restrict__ b1,
    const float* __restrict__ W2,  const float* __restrict__ b2,
    const float* __restrict__ W3,  const float* __restrict__ b3,
    float* __restrict__ out, int out_size)
{
    const int tid  = threadIdx.x;
    const int warp = tid >> 5;
    const int lane = tid & 31;
    const int wm   = warp >> 2;    // M-half: rows wm*32..+31
    const int wn   = warp & 3;     // N-quarter: cols wn*32..+31
    const int row0 = blockIdx.x * TB;

    const uint32_t sb = smem_u32(smem);
    float* xcs = (float*)(smem + XC_OFF);
    float* stg = (float*)(smem + STG_OFF);
    float* w2s = (float*)(smem + W2S_OFF);
    float* w3s = (float*)(smem + W3S_OFF);
    float* b1s = (float*)(smem + B1S_OFF);
    float* b2s = (float*)(smem + B2S_OFF);
    float* b3s = (float*)(smem + B3S_OFF);
    float* zs  = (float*)(smem + ZS_OFF);
    float* as_ = (float*)(smem + AS_OFF);

    // ---- fill A: x -> fp16, XOR-swizzled, row stride 512B ----
    {
        const int r  = tid >> 2;              // 0..63
        const int g0 = (tid & 3) * 8;
        const float* xr = x + (size_t)(row0 + r) * DD;
        unsigned char* ap = smem + A_OFF + r * 512;
        #pragma unroll 4
        for (int i = 0; i < 8; ++i) {
            int g = g0 + i;
            int k0 = g * 8;
            float4 v0 = *(const float4*)(xr + k0);
            float4 v1 = *(const float4*)(xr + k0 + 4);
            uint32_t hu[4];
            hu[0] = pack_h2(v0.x, v0.y);
            hu[1] = pack_h2(v0.z, v0.w);
            hu[2] = pack_h2(v1.x, v1.y);
            hu[3] = pack_h2(v1.z, v1.w);
            uint32_t off = (uint32_t)((g ^ (r & 7)) << 4);
            *(uint4*)(ap + off) = make_uint4(hu[0], hu[1], hu[2], hu[3]);
        }
    }

    // ---- per-lane invariant addresses ----
    const int arow0 = wm * 32 + (lane & 7) + ((lane >> 3) & 1) * 8;   // mt=0 tile
    const uint32_t aBase0 = sb + A_OFF + (uint32_t)arow0 * 512;
    const uint32_t aBase1 = aBase0 + 16 * 512;
    const int aSw = (lane & 7);
    const int bk = (lane & 7) + ((lane >> 3) & 1) * 8;
    const uint32_t bRow = (uint32_t)bk * 256;

    // prefetch: 16B per thread covers the 4KB tile
    auto prefetch = [&](int tix, int b) {
        uint32_t dst = sb + BBUF_OFF + (uint32_t)b * 4096 + (uint32_t)tid * 16;
        const unsigned char* src = g_w1t + (size_t)tix * 4096 + (size_t)tid * 16;
        CP_ASYNC16(dst, src);
    };

    prefetch(0, 0);
    CP_COMMIT();

    float alacc = 0.f;     // log_det partial for row=tid (tid<64)
    int step = 0;

    for (int c = 0; c < 16; ++c) {
        const int l0 = c * 16;

        // ---- small per-layer weights ----
        {
            int jj = tid >> 4, q = tid & 15;
            float4 v4 = make_float4(0.f, 0.f, 0.f, 0.f);
            if (l0 + jj < LL) v4 = ((const float4*)W2)[(l0 + jj) * 16 + q];
            *(float4*)(w2s + jj * W2_STR + q * 4) = v4;
            w3s[jj * W3_STR + q] = (l0 + jj < LL) ? W3[(l0 + jj) * 16 + q] : 0.f;
            if (tid < 128) {
                int jb = tid >> 3, h = tid & 7;
                b1s[tid] = (l0 + jb < LL) ? b1[(l0 + jb) * 8 + h] : 0.f;
                b2s[tid] = (l0 + jb < LL) ? b2[(l0 + jb) * 8 + h] : 0.f;
            }
            if (tid < 32) {
                int j3 = tid >> 1, k3 = tid & 1;
                b3s[tid] = (l0 + j3 < LL) ? b3[(l0 + j3) * 2 + k3] : 0.f;
            }
        }

        float acc[2][4][4];
        #pragma unroll
        for (int mt = 0; mt < 2; ++mt)
            #pragma unroll
            for (int t = 0; t < 4; ++t)
                #pragma unroll
                for (int q = 0; q < 4; ++q) acc[mt][t][q] = 0.f;

        // ---- k loop: one 16-wide step per tile ----
        for (int kt = 0; kt <= c; ++kt) {
            CP_WAIT0();
            __syncthreads();
            {
                int ntix = (kt < c) ? (c * (c + 1) / 2 + kt + 1)
                         : ((c < 15) ? (c + 1) * (c + 2) / 2 : -1);
                if (ntix >= 0) prefetch(ntix, (step + 1) & 1);
                CP_COMMIT();
            }
            const uint32_t buf = sb + BBUF_OFF + (uint32_t)(step & 1) * 4096;

            // A fragments (2 m-tiles)
            uint32_t af[2][4];
            {
                uint32_t offk = (uint32_t)(((2 * kt + (lane >> 4)) ^ aSw) << 4);
                ldsm4(af[0], aBase0 + offk);
                ldsm4(af[1], aBase1 + offk);
            }
            // B fragments: 2 pair-tiles (cols wn*32..+31)
            uint32_t bf[2][4];
            #pragma unroll
            for (int p = 0; p < 2; ++p) {
                uint32_t cidx = (uint32_t)(wn * 4 + 2 * p + (lane >> 4));
                uint32_t off  = bRow + (((cidx ^ (uint32_t)(lane & 7))) << 4);
                ldsm4t(bf[p], buf + off);
            }
            #pragma unroll
            for (int mt = 0; mt < 2; ++mt) {
                #pragma unroll
                for (int p = 0; p < 2; ++p) {
                    mma_f16(acc[mt][2 * p],     af[mt], &bf[p][0]);
                    mma_f16(acc[mt][2 * p + 1], af[mt], &bf[p][2]);
                }
            }
            step++;
        }

        // ---- stage exact fp32 x columns l0+1 .. l0+16 for epilogue ----
        #pragma unroll
        for (int i = 0; i < 4; ++i) {
            int v = tid + i * 256;             // 1024 = 64 rows x 16 cols
            int r = v >> 4, cc = v & 15;
            xcs[r * 17 + cc] = x[(size_t)(row0 + r) * DD + (l0 + 1 + cc)];
        }

        // ---- epilogue: two 64-col passes (wn pairs {0,1} then {2,3}) ----
        #pragma unroll
        for (int p = 0; p < 2; ++p) {
            __syncthreads();
            if ((wn >> 1) == p) {
                const int cbase = (wn & 1) * 32;
                #pragma unroll
                for (int mt = 0; mt < 2; ++mt) {
                    int r = wm * 32 + mt * 16 + (lane >> 2);
                    int cc = (lane & 3) * 2;
                    #pragma unroll
                    for (int t = 0; t < 4; ++t) {
                        *(float2*)(stg + r * 68 + cbase + t * 8 + cc) =
                            make_float2(acc[mt][t][0], acc[mt][t][1]);
                        *(float2*)(stg + (r + 8) * 68 + cbase + t * 8 + cc) =
                            make_float2(acc[mt][t][2], acc[mt][t][3]);
                    }
                }
            }
            __syncthreads();
            // jobs: 512 = 64 rows x 8 local layers, 256 threads -> 2 iters
            #pragma unroll
            for (int it = 0; it < 2; ++it) {
                int job = it * 256 + tid;
                int j   = job & 7;
                int row = job >> 3;
                int jloc = p * 8 + j;
                int l = l0 + jloc;
                float4 q0 = *(const float4*)(stg + row * 68 + j * 8);
                float4 q1 = *(const float4*)(stg + row * 68 + j * 8 + 4);
                if (l < LL) {
                    float pre[8] = {q0.x, q0.y, q0.z, q0.w, q1.x, q1.y, q1.z, q1.w};
                    float h1v[8];
                    #pragma unroll
                    for (int h = 0; h < 8; ++h)
                        h1v[h] = ftanha(pre[h] + b1s[jloc * 8 + h]);
                    unsigned long long a2[4];
                    a2[0] = pk2(b2s[jloc * 8 + 0], b2s[jloc * 8 + 1]);
                    a2[1] = pk2(b2s[jloc * 8 + 2], b2s[jloc * 8 + 3]);
                    a2[2] = pk2(b2s[jloc * 8 + 4], b2s[jloc * 8 + 5]);
                    a2[3] = pk2(b2s[jloc * 8 + 6], b2s[jloc * 8 + 7]);
                    #pragma unroll
                    for (int h = 0; h < 8; ++h) {
                        ulonglong2 rA = *(const ulonglong2*)(w2s + jloc * W2_STR + h * 8);
                        ulonglong2 rB = *(const ulonglong2*)(w2s + jloc * W2_STR + h * 8 + 4);
                        unsigned long long hp = pk2(h1v[h], h1v[h]);
                        fma2(a2[0], hp, rA.x); fma2(a2[1], hp, rA.y);
                        fma2(a2[2], hp, rB.x); fma2(a2[3], hp, rB.y);
                    }
                    float mu = b3s[jloc * 2 + 0], al = b3s[jloc * 2 + 1];
                    #pragma unroll
                    for (int hp4 = 0; hp4 < 4; ++hp4) {
                        float2 pr = up2(a2[hp4]);
                        float h2a = ftanha(pr.x), h2b = ftanha(pr.y);
                        mu += h2a * w3s[jloc * W3_STR + (2 * hp4) * 2]
                            + h2b * w3s[jloc * W3_STR + (2 * hp4 + 1) * 2];
                        al += h2a * w3s[jloc * W3_STR + (2 * hp4) * 2 + 1]
                            + h2b * w3s[jloc * W3_STR + (2 * hp4 + 1) * 2 + 1];
                    }
                    float xn = xcs[row * 17 + jloc];      // exact fp32 x[row][l+1]
                    float zv = (xn - mu) * __expf(-al);
                    zs[row * 17 + (15 - jloc)] = zv;
                    as_[row * 17 + jloc] = al;
                } else {
                    as_[row * 17 + jloc] = 0.f;
                }
            }
        }
        __syncthreads();
        // ---- flush z (coalesced 16-col groups) + alpha accumulation ----
        {
            const int cb = 239 - l0;
            #pragma unroll
            for (int i = 0; i < 4; ++i) {
                int v = tid + i * 256;     // 1024
                int r = v >> 4, cc = v & 15;
                int col = cb + cc;
                if (col >= 0)
                    out[(size_t)(row0 + r) * DD + col] = zs[r * 17 + cc];
            }
            if (tid < 64) {
                float s = 0.f;
                #pragma unroll
                for (int jj = 0; jj < 16; ++jj) s += as_[tid * 17 + jj];
                alacc += s;
            }
        }
    }

    // ---- finals: col 255 + log_det ----
    if (tid < 64) {
        int r = tid;
        float ip0 = ipar[0], ip1 = ipar[1];
        float x0 = x[(size_t)(row0 + r) * DD];           // exact fp32
        out[(size_t)(row0 + r) * DD + 255] = (x0 - ip0) * __expf(-ip1);
        if (out_size > BB * DD)
            out[(size_t)BB * DD + row0 + r] = -(ip1 + alacc);
    }
}

extern "C" void kernel_launch(void* const* d_in, const int* in_sizes, int n_in,
                              void* d_out, int out_size)
{
    const float* x    = (const float*)d_in[0];
    const float* ipar = (const float*)d_in[1];
    const float* W1   = (const float*)d_in[2];
    const float* b1   = (const float*)d_in[3];
    const float* W2   = (const float*)d_in[4];
    const float* b2   = (const float*)d_in[5];
    const float* W3   = (const float*)d_in[6];
    const float* b3   = (const float*)d_in[7];
    float* out = (float*)d_out;

    prep_w1<<<dim3(16, 16), 256>>>(W1);
    cudaFuncSetAttribute(maf_kernel, cudaFuncAttributeMaxDynamicSharedMemorySize, SMEM_TOTAL);
    maf_kernel<<<BB / TB, NT, SMEM_TOTAL>>>(x, ipar, W1, b1, W2, b2, W3, b3, out, out_size);
}